// round 13
// baseline (speedup 1.0000x reference)
#include <cuda_runtime.h>
#include <cuda_fp16.h>
#include <cstdint>

#define B_    16
#define CIN_  512
#define COUT_ 512
#define LAT_  512

#define XROWS  18496            // 16 * 34 * 34
#define XGUARD 64               // front zero rows
#define XTAIL  320              // tail zero rows (covers 256-row B tiles past end)
#define NT2    73               // ceil(18496/256)

// ---------------- device globals (allocation-free scratch) ------------------
__device__ float g_s[B_ * CIN_];
__device__ float g_wsq[COUT_ * CIN_];
__device__ float g_d[B_ * COUT_];
__device__ __half g_y[(size_t)B_ * COUT_ * 4 * 1156];    // [b][co][p][34][34] fp16

__device__ __align__(256) __half g_Ah[9ull * 512 * 512];   // [tap][co][ci]
__device__ __align__(256) __half g_Xh[(size_t)(XGUARD + XROWS + XTAIL) * 512];

// tap order grouped by parity: p0={0,2,6,8} p1={1,7} p2={3,5} p3={4}
__constant__ int c_tap[9]   = {0, 2, 6, 8, 1, 7, 3, 5, 4};
// shift[t] = (kh>>1)*34 + (kw>>1), indexed by tap id
__constant__ int c_shift[9] = {0, 0, 1, 0, 0, 1, 34, 34, 35};

// ---------------- helpers ---------------------------------------------------
__device__ __forceinline__ uint32_t smem_to_u32(const void* p) {
    uint32_t a;
    asm("{ .reg .u64 t; cvta.to.shared.u64 t, %1; cvt.u32.u64 %0, t; }"
        : "=r"(a) : "l"(p));
    return a;
}
__device__ __forceinline__ void cp16(uint32_t dst, const void* src) {
    asm volatile("cp.async.cg.shared.global [%0], [%1], 16;\n"
                 :: "r"(dst), "l"(src));
}
__device__ __forceinline__ void cp_commit() {
    asm volatile("cp.async.commit_group;\n" ::: "memory");
}
__device__ __forceinline__ void cp_wait2() {
    asm volatile("cp.async.wait_group 2;\n" ::: "memory");
}
__device__ __forceinline__ void ldsm_x4(uint32_t* r, uint32_t addr) {
    asm volatile("ldmatrix.sync.aligned.m8n8.x4.shared.b16 {%0,%1,%2,%3}, [%4];"
                 : "=r"(r[0]), "=r"(r[1]), "=r"(r[2]), "=r"(r[3]) : "r"(addr));
}
__device__ __forceinline__ void mma_fp16(float* d, const uint32_t* a,
                                         const uint32_t* b) {
    asm volatile(
        "mma.sync.aligned.m16n8k16.row.col.f32.f16.f16.f32 "
        "{%0,%1,%2,%3}, {%4,%5,%6,%7}, {%8,%9}, {%0,%1,%2,%3};"
        : "+f"(d[0]), "+f"(d[1]), "+f"(d[2]), "+f"(d[3])
        : "r"(a[0]), "r"(a[1]), "r"(a[2]), "r"(a[3]), "r"(b[0]), "r"(b[1]));
}
// smem tile rows of 64 fp16 (128B), xor-swizzled 16B chunks, 8-row period
__device__ __forceinline__ int swz(int row, int c8) {
    return row * 128 + ((c8 ^ (row & 7)) << 4);
}

// ---------------------------------------------------------------------------
__global__ void k_style(const float* __restrict__ w, const float* __restrict__ aw,
                        const float* __restrict__ ab) {
    int b = blockIdx.x, ci = threadIdx.x;
    const float* wr = w + b * LAT_;
    const float* ar = aw + (size_t)ci * LAT_;
    float acc = 0.f;
#pragma unroll 8
    for (int l = 0; l < LAT_; ++l) acc += wr[l] * ar[l];
    g_s[b * CIN_ + ci] = acc + ab[ci] + 1.0f;
}

__global__ void k_demod() {
    int b = blockIdx.x, co = threadIdx.x;
    __shared__ float s2[CIN_];
    for (int i = threadIdx.x; i < CIN_; i += blockDim.x) {
        float v = g_s[b * CIN_ + i];
        s2[i] = v * v;
    }
    __syncthreads();
    const float* wq = g_wsq + (size_t)co * CIN_;
    float a = 0.f;
#pragma unroll 8
    for (int ci = 0; ci < CIN_; ++ci) a += s2[ci] * wq[ci];
    g_d[b * COUT_ + co] = rsqrtf(a + 1e-8f);
}

// A prep + wsq (merged): g_Ah[tap][co][ci] = fp16(weight[co][ci][tap]),
// g_wsq[co][ci] = sum_t weight^2
__global__ __launch_bounds__(256) void k_prepw(const float* __restrict__ weight) {
    const int co = blockIdx.x;
#pragma unroll
    for (int r = 0; r < 2; ++r) {
        const int ci = threadIdx.x * 2 + r;
        const float* p = weight + ((size_t)co * 512 + ci) * 9;
        float sq = 0.f;
#pragma unroll
        for (int t = 0; t < 9; ++t) {
            float v = p[t];
            g_Ah[((size_t)t * 512 + co) * 512 + ci] = __float2half_rn(v);
            sq += v * v;
        }
        g_wsq[(size_t)co * 512 + ci] = sq;
    }
}

// Xp prep: row n = b*1156 + r*34 + c ; Xp = x*s interior, 0 on r,c in {0,33}
__global__ __launch_bounds__(256) void k_prepx(const float* __restrict__ x) {
    __shared__ float xt[256][33];
    const int r = blockIdx.x;          // 0..33
    const int b = blockIdx.y;
    const int tid = threadIdx.x;
    const bool irow = (r >= 1 && r <= 32);
    for (int half = 0; half < 2; ++half) {
        const int cb = half * 256;
        __syncthreads();
        if (irow) {
            for (int idx = tid; idx < 256 * 32; idx += 256) {
                int ci = idx >> 5, cc = idx & 31;
                xt[ci][cc] = x[((size_t)(b * 512 + cb + ci) * 32 + (r - 1)) * 32 + cc]
                             * g_s[b * 512 + cb + ci];
            }
        }
        __syncthreads();
        for (int idx = tid; idx < 34 * 256; idx += 256) {
            int c = idx >> 8, ci = idx & 255;
            float v = (irow && c >= 1 && c <= 32) ? xt[ci][c - 1] : 0.f;
            size_t o = ((size_t)(b * 1156 + r * 34 + c) + XGUARD) * 512 + cb + ci;
            g_Xh[o] = __float2half_rn(v);
        }
    }
}

__global__ void k_guard() {
    int idx = blockIdx.x * 256 + threadIdx.x;       // (64+320)*512 = 196608 total
    __half z = __float2half_rn(0.f);
    if (idx < XGUARD * 512) {
        g_Xh[idx] = z;
    } else {
        g_Xh[(size_t)(XGUARD + XROWS) * 512 + (idx - XGUARD * 512)] = z;
    }
}

// ---------------------------------------------------------------------------
// Block tile: 128 co x 256 n x K-chunk 64. 512 threads, 16 warps.
// Warp tile 32x64 (4x4 arrangement): acc = 64 regs/thread -> ptxas has
// scheduling slack to hoist ldsm over MMA batches; 4 warps/SMSP hide the rest.
#define STAGES      4
#define TILE_A      0           // 128 x 64 fp16 = 16KB
#define TILE_B      16384       // 256 x 64 fp16 = 32KB
#define STAGE_BYTES 49152
#define NCHUNK      72          // 9 taps x 8 chunks of 64 ci

__device__ __forceinline__ void load_chunk(uint32_t su, int stage, int g,
                                           int co0, int n0, int tid) {
    const int tap = c_tap[g >> 3];
    const int kc  = (g & 7) << 6;
    const uint32_t sb = su + stage * STAGE_BYTES;
    // A: 128 rows x 8 c8 = 1024 cp16 over 512 threads
#pragma unroll
    for (int t = 0; t < 2; ++t) {
        int idx = t * 512 + tid;
        int row = idx >> 3, c8 = idx & 7;
        size_t aoff = ((size_t)(tap * 512 + co0 + row)) * 512 + kc + c8 * 8;
        cp16(sb + TILE_A + swz(row, c8), g_Ah + aoff);
    }
    // B: 256 rows x 8 c8 = 2048 cp16 (shifted view into padded X)
    const long base = (long)n0 - c_shift[tap] + XGUARD;
#pragma unroll
    for (int t = 0; t < 4; ++t) {
        int idx = t * 512 + tid;
        int row = idx >> 3, c8 = idx & 7;
        size_t boff = (size_t)(base + row) * 512 + kc + c8 * 8;
        cp16(sb + TILE_B + swz(row, c8), g_Xh + boff);
    }
}

__device__ __forceinline__ void do_compute(uint32_t sb, float acc[2][8][4],
                                           int lane, int warp_m, int warp_n) {
#pragma unroll
    for (int ks = 0; ks < 4; ++ks) {
        uint32_t bh[16];
#pragma unroll
        for (int pr = 0; pr < 4; ++pr) {
            int brow = warp_n + pr * 16 + (lane & 7) + ((lane >> 4) & 1) * 8;
            int bc8  = ks * 2 + ((lane >> 3) & 1);
            ldsm_x4(&bh[pr * 4], sb + TILE_B + swz(brow, bc8));
        }
#pragma unroll
        for (int mt = 0; mt < 2; ++mt) {
            int arow = warp_m + mt * 16 + (lane & 15);
            int ac8  = ks * 2 + ((lane >> 4) & 1);
            uint32_t ah[4];
            ldsm_x4(ah, sb + TILE_A + swz(arow, ac8));
#pragma unroll
            for (int nt = 0; nt < 8; ++nt) {
                mma_fp16(acc[mt][nt], ah, &bh[(nt >> 1) * 4 + (nt & 1) * 2]);
            }
        }
    }
}

__device__ __forceinline__ void epilogue(float acc[2][8][4], int p, int co0,
                                         int n0, int lane, int warp_m, int warp_n) {
    const int rr = lane >> 2, q = lane & 3;
#pragma unroll
    for (int mt = 0; mt < 2; ++mt) {
        const int co = co0 + warp_m + mt * 16 + rr;
#pragma unroll
        for (int nt = 0; nt < 8; ++nt) {
            int n = n0 + warp_n + nt * 8 + q * 2;
            if (n < XROWS) {
                int b = n / 1156;
                int rem = n - b * 1156;   // even: half2 stays in-row and aligned
                __half2 v0 = __floats2half2_rn(acc[mt][nt][0], acc[mt][nt][1]);
                __half2 v1 = __floats2half2_rn(acc[mt][nt][2], acc[mt][nt][3]);
                *(__half2*)(g_y + (((size_t)(b * 512 + co) * 4 + p) * 1156 + rem)) = v0;
                *(__half2*)(g_y + (((size_t)(b * 512 + co + 8) * 4 + p) * 1156 + rem)) = v1;
            }
        }
    }
}

__global__ __launch_bounds__(512, 1) void k_gemm() {
    extern __shared__ char smem[];
    const uint32_t su = smem_to_u32(smem);
    const int tid = threadIdx.x;
    const int lane = tid & 31, wid = tid >> 5;
    const int warp_m = (wid >> 2) * 32;   // 4 m-slots of 32 rows
    const int warp_n = (wid & 3) * 64;    // 4 n-slots of 64 cols
    const int n0  = blockIdx.x * 256;
    const int co0 = blockIdx.y * 128;

    float acc[2][8][4];
#pragma unroll
    for (int a = 0; a < 2; ++a)
#pragma unroll
        for (int b = 0; b < 8; ++b)
#pragma unroll
            for (int c = 0; c < 4; ++c) acc[a][b][c] = 0.f;

#pragma unroll
    for (int s = 0; s < STAGES - 1; ++s) {
        load_chunk(su, s, s, co0, n0, tid);
        cp_commit();
    }

    for (int g = 0; g < NCHUNK; ++g) {
        cp_wait2();                       // oldest (chunk g) resident, 2 pending
        __syncthreads();                  // single barrier per chunk
        if (g + STAGES - 1 < NCHUNK)
            load_chunk(su, (g + STAGES - 1) % STAGES, g + STAGES - 1, co0, n0, tid);
        cp_commit();
        do_compute(su + (g % STAGES) * STAGE_BYTES, acc, lane, warp_m, warp_n);
        if (g == 31 || g == 47 || g == 63 || g == 71) {
            const int p = (g == 31) ? 0 : (g == 47) ? 1 : (g == 63) ? 2 : 3;
            epilogue(acc, p, co0, n0, lane, warp_m, warp_n);
#pragma unroll
            for (int a = 0; a < 2; ++a)
#pragma unroll
                for (int b = 0; b < 8; ++b)
#pragma unroll
                    for (int c = 0; c < 4; ++c) acc[a][b][c] = 0.f;
        }
    }
}

// ---------------------------------------------------------------------------
__global__ __launch_bounds__(256) void k_blur(float* __restrict__ z,
                                              const float* __restrict__ bias) {
    __shared__ float ys[67][68];
    const int co = blockIdx.x, b = blockIdx.y;
    const int tid = threadIdx.x;

    for (int idx = tid; idx < 67 * 68; idx += 256) ((float*)ys)[idx] = 0.f;
    __syncthreads();

    const __half* yb = g_y + ((size_t)(b * 512 + co)) * 4 * 1156;
    for (int idx = tid; idx < 4 * 33 * 33; idx += 256) {
        int p = idx / 1089, rem = idx - p * 1089;
        int i = rem / 33, j = rem - i * 33;
        float v = __half2float(yb[(size_t)p * 1156 + (i + 1) * 34 + (j + 1)]);
        ys[2 * i + (p >> 1) + 1][2 * j + (p & 1) + 1] = v;
    }
    __syncthreads();

    const float dd = g_d[b * COUT_ + co];
    const float bv = bias[co];
    const int u = tid >> 2;
    const int v0 = (tid & 3) * 16;

    float col[19];
#pragma unroll
    for (int m = 0; m < 19; ++m) {
        col[m] = ys[u][v0 + m] + 3.f * ys[u + 1][v0 + m]
               + 3.f * ys[u + 2][v0 + m] + ys[u + 3][v0 + m];
    }
    float* zp = z + (((size_t)b * COUT_ + co) * 64 + u) * 64 + v0;
#pragma unroll
    for (int m = 0; m < 16; ++m) {
        float h = col[m] + 3.f * col[m + 1] + 3.f * col[m + 2] + col[m + 3];
        zp[m] = dd * (h * (1.f / 16.f)) + bv;
    }
}

// ---------------------------------------------------------------------------
extern "C" void kernel_launch(void* const* d_in, const int* in_sizes, int n_in,
                              void* d_out, int out_size) {
    const float* x    = (const float*)d_in[0];
    const float* w    = (const float*)d_in[1];
    const float* wt   = (const float*)d_in[2];
    const float* bias = (const float*)d_in[3];
    const float* aw   = (const float*)d_in[4];
    const float* ab   = (const float*)d_in[5];
    float* z = (float*)d_out;

    cudaFuncSetAttribute(k_gemm, cudaFuncAttributeMaxDynamicSharedMemorySize,
                         STAGES * STAGE_BYTES);

    k_style<<<B_, CIN_>>>(w, aw, ab);
    k_prepx<<<dim3(34, B_), 256>>>(x);
    k_guard<<<768, 256>>>();
    k_prepw<<<COUT_, 256>>>(wt);
    k_demod<<<B_, COUT_>>>();
    k_gemm<<<dim3(NT2, 4), 512, STAGES * STAGE_BYTES>>>();
    k_blur<<<dim3(COUT_, B_), 256>>>(z, bias);
}

// round 14
// speedup vs baseline: 1.0591x; 1.0591x over previous
#include <cuda_runtime.h>
#include <cuda_fp16.h>
#include <cstdint>

#define B_    16
#define CIN_  512
#define COUT_ 512
#define LAT_  512

#define XROWS  18496            // 16 * 34 * 34
#define XGUARD 64               // front zero rows
#define XTAIL  320              // tail zero rows (covers 256-row B tiles past end)
#define NT2    73               // ceil(18496/256)

// ---------------- device globals (allocation-free scratch) ------------------
__device__ float g_s[B_ * CIN_];
__device__ float g_wsq[COUT_ * CIN_];
__device__ float g_d[B_ * COUT_];
__device__ __half g_y[(size_t)B_ * COUT_ * 4 * 1156];    // [b][co][p][34][34] fp16

__device__ __align__(256) __half g_Ah[9ull * 512 * 512];   // [tap][co][ci]
__device__ __align__(256) __half g_Xh[(size_t)(XGUARD + XROWS + XTAIL) * 512];

// tap order grouped by parity: p0={0,2,6,8} p1={1,7} p2={3,5} p3={4}
__constant__ int c_tap[9]   = {0, 2, 6, 8, 1, 7, 3, 5, 4};
// shift[t] = (kh>>1)*34 + (kw>>1), indexed by tap id
__constant__ int c_shift[9] = {0, 0, 1, 0, 0, 1, 34, 34, 35};

// ---------------- helpers ---------------------------------------------------
__device__ __forceinline__ uint32_t smem_to_u32(const void* p) {
    uint32_t a;
    asm("{ .reg .u64 t; cvta.to.shared.u64 t, %1; cvt.u32.u64 %0, t; }"
        : "=r"(a) : "l"(p));
    return a;
}
__device__ __forceinline__ void cp16(uint32_t dst, const void* src) {
    asm volatile("cp.async.cg.shared.global [%0], [%1], 16;\n"
                 :: "r"(dst), "l"(src));
}
__device__ __forceinline__ void cp_commit() {
    asm volatile("cp.async.commit_group;\n" ::: "memory");
}
__device__ __forceinline__ void cp_wait2() {
    asm volatile("cp.async.wait_group 2;\n" ::: "memory");
}
__device__ __forceinline__ void ldsm_x4(uint32_t* r, uint32_t addr) {
    asm volatile("ldmatrix.sync.aligned.m8n8.x4.shared.b16 {%0,%1,%2,%3}, [%4];"
                 : "=r"(r[0]), "=r"(r[1]), "=r"(r[2]), "=r"(r[3]) : "r"(addr));
}
__device__ __forceinline__ void mma_fp16(float* d, const uint32_t* a,
                                         const uint32_t* b) {
    asm volatile(
        "mma.sync.aligned.m16n8k16.row.col.f32.f16.f16.f32 "
        "{%0,%1,%2,%3}, {%4,%5,%6,%7}, {%8,%9}, {%0,%1,%2,%3};"
        : "+f"(d[0]), "+f"(d[1]), "+f"(d[2]), "+f"(d[3])
        : "r"(a[0]), "r"(a[1]), "r"(a[2]), "r"(a[3]), "r"(b[0]), "r"(b[1]));
}
// smem tile rows of 64 fp16 (128B), xor-swizzled 16B chunks, 8-row period
__device__ __forceinline__ int swz(int row, int c8) {
    return row * 128 + ((c8 ^ (row & 7)) << 4);
}

// ---------------------------------------------------------------------------
// Launch 1: style (blocks 0..15) + prepw/wsq (blocks 16..527)
__global__ __launch_bounds__(512) void k_sw(const float* __restrict__ w,
                                            const float* __restrict__ aw,
                                            const float* __restrict__ ab,
                                            const float* __restrict__ weight) {
    const int bx = blockIdx.x, tid = threadIdx.x;
    if (bx < 16) {
        // style: s[b,ci] = w[b,:] . affine_w[ci,:] + affine_b[ci] + 1
        const int b = bx, ci = tid;
        const float* wr = w + b * LAT_;
        const float* ar = aw + (size_t)ci * LAT_;
        float acc = 0.f;
#pragma unroll 8
        for (int l = 0; l < LAT_; ++l) acc += wr[l] * ar[l];
        g_s[b * CIN_ + ci] = acc + ab[ci] + 1.0f;
    } else {
        // prepw: g_Ah[tap][co][ci] = fp16(weight[co][ci][tap]); wsq = sum w^2
        const int co = bx - 16, ci = tid;
        const float* p = weight + ((size_t)co * 512 + ci) * 9;
        float sq = 0.f;
#pragma unroll
        for (int t = 0; t < 9; ++t) {
            float v = p[t];
            g_Ah[((size_t)t * 512 + co) * 512 + ci] = __float2half_rn(v);
            sq += v * v;
        }
        g_wsq[(size_t)co * 512 + ci] = sq;
    }
}

// ---------------------------------------------------------------------------
// Launch 2: prepx (x=0..33) + guard (x==34) + demod (x==35); grid (36, B_)
__global__ __launch_bounds__(512) void k_px(const float* __restrict__ x) {
    __shared__ float xt[256][33];
    const int r = blockIdx.x;
    const int b = blockIdx.y;
    const int tid = threadIdx.x;

    if (r == 35) {
        // demod: d[b,co] = rsqrt(sum_ci s^2 * wsq + 1e-8)
        __shared__ float s2[CIN_];
        const int co = tid;
        {
            float v = g_s[b * CIN_ + tid];
            s2[tid] = v * v;
        }
        __syncthreads();
        const float* wq = g_wsq + (size_t)co * CIN_;
        float a = 0.f;
#pragma unroll 8
        for (int ci = 0; ci < CIN_; ++ci) a += s2[ci] * wq[ci];
        g_d[b * COUT_ + co] = rsqrtf(a + 1e-8f);
        return;
    }
    if (r == 34) {
        // guard zeroing: slice b of the 196608 guard halves
        const __half z = __float2half_rn(0.f);
        const int base = b * 12288;
        for (int k = tid; k < 12288; k += 512) {
            int idx = base + k;
            if (idx < XGUARD * 512)
                g_Xh[idx] = z;
            else
                g_Xh[(size_t)(XGUARD + XROWS) * 512 + (idx - XGUARD * 512)] = z;
        }
        return;
    }

    // prepx: row n = b*1156 + r*34 + c ; Xp = x*s interior, 0 on r,c in {0,33}
    const bool irow = (r >= 1 && r <= 32);
    for (int half = 0; half < 2; ++half) {
        const int cb = half * 256;
        __syncthreads();
        if (irow) {
            for (int idx = tid; idx < 256 * 32; idx += 512) {
                int ci = idx >> 5, cc = idx & 31;
                xt[ci][cc] = x[((size_t)(b * 512 + cb + ci) * 32 + (r - 1)) * 32 + cc]
                             * g_s[b * 512 + cb + ci];
            }
        }
        __syncthreads();
        for (int idx = tid; idx < 34 * 256; idx += 512) {
            int c = idx >> 8, ci = idx & 255;
            float v = (irow && c >= 1 && c <= 32) ? xt[ci][c - 1] : 0.f;
            size_t o = ((size_t)(b * 1156 + r * 34 + c) + XGUARD) * 512 + cb + ci;
            g_Xh[o] = __float2half_rn(v);
        }
    }
}

// ---------------------------------------------------------------------------
// Launch 3: GEMM. Block tile 128 co x 256 n x K-chunk 64, 8 warps (2x4),
// warp tile 64x64, STAGES=4 (byte-identical to the 703us champion).
#define STAGES      4
#define TILE_A      0           // 128 x 64 fp16 = 16KB
#define TILE_B      16384       // 256 x 64 fp16 = 32KB
#define STAGE_BYTES 49152
#define NCHUNK      72          // 9 taps x 8 chunks of 64 ci

__device__ __forceinline__ void load_chunk(uint32_t su, int stage, int g,
                                           int co0, int n0, int tid) {
    const int tap = c_tap[g >> 3];
    const int kc  = (g & 7) << 6;
    const uint32_t sb = su + stage * STAGE_BYTES;
#pragma unroll
    for (int t = 0; t < 4; ++t) {
        int idx = t * 256 + tid;
        int row = idx >> 3, c8 = idx & 7;
        size_t aoff = ((size_t)(tap * 512 + co0 + row)) * 512 + kc + c8 * 8;
        cp16(sb + TILE_A + swz(row, c8), g_Ah + aoff);
    }
    const long base = (long)n0 - c_shift[tap] + XGUARD;
#pragma unroll
    for (int t = 0; t < 8; ++t) {
        int idx = t * 256 + tid;
        int row = idx >> 3, c8 = idx & 7;
        size_t boff = (size_t)(base + row) * 512 + kc + c8 * 8;
        cp16(sb + TILE_B + swz(row, c8), g_Xh + boff);
    }
}

__device__ __forceinline__ void do_compute(uint32_t sb, float acc[4][8][4],
                                           int lane, int warp_m, int warp_n) {
#pragma unroll
    for (int ks = 0; ks < 4; ++ks) {
        uint32_t bh[16];
#pragma unroll
        for (int pr = 0; pr < 4; ++pr) {
            int brow = warp_n + pr * 16 + (lane & 7) + ((lane >> 4) & 1) * 8;
            int bc8  = ks * 2 + ((lane >> 3) & 1);
            ldsm_x4(&bh[pr * 4], sb + TILE_B + swz(brow, bc8));
        }
#pragma unroll
        for (int mt = 0; mt < 4; ++mt) {
            int arow = warp_m + mt * 16 + (lane & 15);
            int ac8  = ks * 2 + ((lane >> 4) & 1);
            uint32_t ah[4];
            ldsm_x4(ah, sb + TILE_A + swz(arow, ac8));
#pragma unroll
            for (int nt = 0; nt < 8; ++nt) {
                mma_fp16(acc[mt][nt], ah, &bh[(nt >> 1) * 4 + (nt & 1) * 2]);
            }
        }
    }
}

__device__ __forceinline__ void epilogue(float acc[4][8][4], int p, int co0,
                                         int n0, int lane, int warp_m, int warp_n) {
    const int rr = lane >> 2, q = lane & 3;
#pragma unroll
    for (int mt = 0; mt < 4; ++mt) {
        const int co = co0 + warp_m + mt * 16 + rr;
#pragma unroll
        for (int nt = 0; nt < 8; ++nt) {
            int n = n0 + warp_n + nt * 8 + q * 2;
            if (n < XROWS) {
                int b = n / 1156;
                int rem = n - b * 1156;   // even: half2 stays in-row and aligned
                __half2 v0 = __floats2half2_rn(acc[mt][nt][0], acc[mt][nt][1]);
                __half2 v1 = __floats2half2_rn(acc[mt][nt][2], acc[mt][nt][3]);
                *(__half2*)(g_y + (((size_t)(b * 512 + co) * 4 + p) * 1156 + rem)) = v0;
                *(__half2*)(g_y + (((size_t)(b * 512 + co + 8) * 4 + p) * 1156 + rem)) = v1;
            }
        }
    }
}

__global__ __launch_bounds__(256, 1) void k_gemm() {
    extern __shared__ char smem[];
    const uint32_t su = smem_to_u32(smem);
    const int tid = threadIdx.x;
    const int lane = tid & 31, wid = tid >> 5;
    const int warp_m = (wid >> 2) * 64;
    const int warp_n = (wid & 3) * 64;
    const int n0  = blockIdx.x * 256;
    const int co0 = blockIdx.y * 128;

    float acc[4][8][4];
#pragma unroll
    for (int a = 0; a < 4; ++a)
#pragma unroll
        for (int b = 0; b < 8; ++b)
#pragma unroll
            for (int c = 0; c < 4; ++c) acc[a][b][c] = 0.f;

#pragma unroll
    for (int s = 0; s < STAGES - 1; ++s) {
        load_chunk(su, s, s, co0, n0, tid);
        cp_commit();
    }

    for (int g = 0; g < NCHUNK; ++g) {
        cp_wait2();                       // oldest (chunk g) resident, 2 pending
        __syncthreads();                  // single barrier per chunk
        if (g + STAGES - 1 < NCHUNK)
            load_chunk(su, (g + STAGES - 1) % STAGES, g + STAGES - 1, co0, n0, tid);
        cp_commit();
        do_compute(su + (g % STAGES) * STAGE_BYTES, acc, lane, warp_m, warp_n);
        if (g == 31 || g == 47 || g == 63 || g == 71) {
            const int p = (g == 31) ? 0 : (g == 47) ? 1 : (g == 63) ? 2 : 3;
            epilogue(acc, p, co0, n0, lane, warp_m, warp_n);
#pragma unroll
            for (int a = 0; a < 4; ++a)
#pragma unroll
                for (int b = 0; b < 8; ++b)
#pragma unroll
                    for (int c = 0; c < 4; ++c) acc[a][b][c] = 0.f;
        }
    }
}

// ---------------------------------------------------------------------------
// Launch 4 (profiled next round): blur. Border-only zeroing — the demux
// provably writes every interior cell rows 1..66 x cols 1..66; reads touch
// only row 0 and col 0 beyond that.
__global__ __launch_bounds__(256) void k_blur(float* __restrict__ z,
                                              const float* __restrict__ bias) {
    __shared__ float ys[67][68];
    const int co = blockIdx.x, b = blockIdx.y;
    const int tid = threadIdx.x;

    // zero 134 border cells: row 0 (68 cols), col 0 rows 1..66 (66 cells)
    if (tid < 134) {
        if (tid < 68) ys[0][tid] = 0.f;
        else ys[tid - 67][0] = 0.f;       // rows 1..66
    }
    __syncthreads();

    const __half* yb = g_y + ((size_t)(b * 512 + co)) * 4 * 1156;
    for (int idx = tid; idx < 4 * 33 * 33; idx += 256) {
        int p = idx / 1089, rem = idx - p * 1089;
        int i = rem / 33, j = rem - i * 33;
        float v = __half2float(yb[(size_t)p * 1156 + (i + 1) * 34 + (j + 1)]);
        ys[2 * i + (p >> 1) + 1][2 * j + (p & 1) + 1] = v;
    }
    __syncthreads();

    const float dd = g_d[b * COUT_ + co];
    const float bv = bias[co];
    const int u = tid >> 2;
    const int v0 = (tid & 3) * 16;

    float col[19];
#pragma unroll
    for (int m = 0; m < 19; ++m) {
        col[m] = ys[u][v0 + m] + 3.f * ys[u + 1][v0 + m]
               + 3.f * ys[u + 2][v0 + m] + ys[u + 3][v0 + m];
    }
    float* zp = z + (((size_t)b * COUT_ + co) * 64 + u) * 64 + v0;
#pragma unroll
    for (int m = 0; m < 16; ++m) {
        float h = col[m] + 3.f * col[m + 1] + 3.f * col[m + 2] + col[m + 3];
        zp[m] = dd * (h * (1.f / 16.f)) + bv;
    }
}

// ---------------------------------------------------------------------------
extern "C" void kernel_launch(void* const* d_in, const int* in_sizes, int n_in,
                              void* d_out, int out_size) {
    const float* x    = (const float*)d_in[0];
    const float* w    = (const float*)d_in[1];
    const float* wt   = (const float*)d_in[2];
    const float* bias = (const float*)d_in[3];
    const float* aw   = (const float*)d_in[4];
    const float* ab   = (const float*)d_in[5];
    float* z = (float*)d_out;

    cudaFuncSetAttribute(k_gemm, cudaFuncAttributeMaxDynamicSharedMemorySize,
                         STAGES * STAGE_BYTES);

    // 4 launches; k_blur is our 4th -> ncu (-s 5 -c 1) profiles it next round.
    k_sw<<<16 + COUT_, 512>>>(w, aw, ab, wt);               // 1: style + prepw
    k_px<<<dim3(36, B_), 512>>>(x);                         // 2: prepx+guard+demod
    k_gemm<<<dim3(NT2, 4), 256, STAGES * STAGE_BYTES>>>();  // 3
    k_blur<<<dim3(COUT_, B_), 256>>>(z, bias);              // 4  <- profile target
}

// round 15
// speedup vs baseline: 1.7080x; 1.6127x over previous
#include <cuda_runtime.h>
#include <cuda_fp16.h>
#include <cstdint>

#define B_    16
#define CIN_  512
#define COUT_ 512
#define LAT_  512

#define XROWS  18496            // 16 * 34 * 34
#define XGUARD 64               // front zero rows
#define XTAIL  320              // tail zero rows (covers 256-row B tiles past end)
#define NT2    73               // ceil(18496/256)

// ---------------- device globals (allocation-free scratch) ------------------
__device__ float g_s[B_ * CIN_];
__device__ float g_wsq[COUT_ * CIN_];
__device__ float g_d[B_ * COUT_];
__device__ __half g_y[(size_t)B_ * COUT_ * 4 * 1156];    // [b][co][p][34][34] fp16

__device__ __align__(256) __half g_Ah[9ull * 512 * 512];   // [tap][co][ci]
__device__ __align__(256) __half g_Xh[(size_t)(XGUARD + XROWS + XTAIL) * 512];

// tap order grouped by parity: p0={0,2,6,8} p1={1,7} p2={3,5} p3={4}
__constant__ int c_tap[9]   = {0, 2, 6, 8, 1, 7, 3, 5, 4};
// shift[t] = (kh>>1)*34 + (kw>>1), indexed by tap id
__constant__ int c_shift[9] = {0, 0, 1, 0, 0, 1, 34, 34, 35};

// ---------------- helpers ---------------------------------------------------
__device__ __forceinline__ uint32_t smem_to_u32(const void* p) {
    uint32_t a;
    asm("{ .reg .u64 t; cvta.to.shared.u64 t, %1; cvt.u32.u64 %0, t; }"
        : "=r"(a) : "l"(p));
    return a;
}
__device__ __forceinline__ void cp16(uint32_t dst, const void* src) {
    asm volatile("cp.async.cg.shared.global [%0], [%1], 16;\n"
                 :: "r"(dst), "l"(src));
}
__device__ __forceinline__ void cp_commit() {
    asm volatile("cp.async.commit_group;\n" ::: "memory");
}
__device__ __forceinline__ void cp_wait2() {
    asm volatile("cp.async.wait_group 2;\n" ::: "memory");
}
__device__ __forceinline__ void ldsm_x4(uint32_t* r, uint32_t addr) {
    asm volatile("ldmatrix.sync.aligned.m8n8.x4.shared.b16 {%0,%1,%2,%3}, [%4];"
                 : "=r"(r[0]), "=r"(r[1]), "=r"(r[2]), "=r"(r[3]) : "r"(addr));
}
__device__ __forceinline__ void mma_fp16(float* d, const uint32_t* a,
                                         const uint32_t* b) {
    asm volatile(
        "mma.sync.aligned.m16n8k16.row.col.f32.f16.f16.f32 "
        "{%0,%1,%2,%3}, {%4,%5,%6,%7}, {%8,%9}, {%0,%1,%2,%3};"
        : "+f"(d[0]), "+f"(d[1]), "+f"(d[2]), "+f"(d[3])
        : "r"(a[0]), "r"(a[1]), "r"(a[2]), "r"(a[3]), "r"(b[0]), "r"(b[1]));
}
// smem tile rows of 64 fp16 (128B), xor-swizzled 16B chunks, 8-row period
__device__ __forceinline__ int swz(int row, int c8) {
    return row * 128 + ((c8 ^ (row & 7)) << 4);
}

// ---------------------------------------------------------------------------
// Launch 1: style (blocks 0..15, warp-cooperative coalesced) +
//           prepw/wsq (blocks 16..527)
__global__ __launch_bounds__(512) void k_sw(const float* __restrict__ w,
                                            const float* __restrict__ aw,
                                            const float* __restrict__ ab,
                                            const float* __restrict__ weight) {
    const int bx = blockIdx.x, tid = threadIdx.x;
    if (bx < 16) {
        __shared__ float sw[512];
        const int b = bx;
        sw[tid] = w[b * 512 + tid];
        __syncthreads();
        const int lane = tid & 31, wp = tid >> 5;   // 16 warps x 32 ci
        for (int cc = 0; cc < 32; ++cc) {
            const int ci = wp * 32 + cc;
            const float4* ar = (const float4*)(aw + (size_t)ci * 512);
            float acc = 0.f;
#pragma unroll
            for (int m = 0; m < 4; ++m) {
                float4 v  = ar[lane + 32 * m];
                float4 s4 = ((const float4*)sw)[lane + 32 * m];
                acc += v.x * s4.x + v.y * s4.y + v.z * s4.z + v.w * s4.w;
            }
#pragma unroll
            for (int o = 16; o; o >>= 1) acc += __shfl_down_sync(~0u, acc, o);
            if (lane == 0) g_s[b * 512 + ci] = acc + ab[ci] + 1.0f;
        }
    } else {
        // prepw: g_Ah[tap][co][ci] = fp16(weight[co][ci][tap]); wsq = sum w^2
        const int co = bx - 16, ci = tid;
        const float* p = weight + ((size_t)co * 512 + ci) * 9;
        float sq = 0.f;
#pragma unroll
        for (int t = 0; t < 9; ++t) {
            float v = p[t];
            g_Ah[((size_t)t * 512 + co) * 512 + ci] = __float2half_rn(v);
            sq += v * v;
        }
        g_wsq[(size_t)co * 512 + ci] = sq;
    }
}

// ---------------------------------------------------------------------------
// Launch 2: prepx (x=0..33) + guard (x==34) + demod (x==35, warp-coop);
// grid (36, B_)
__global__ __launch_bounds__(512) void k_px(const float* __restrict__ x) {
    __shared__ float xt[256][33];
    const int r = blockIdx.x;
    const int b = blockIdx.y;
    const int tid = threadIdx.x;

    if (r == 35) {
        // demod: d[b,co] = rsqrt(sum_ci s^2 * wsq + 1e-8), coalesced
        __shared__ float s2[CIN_];
        {
            float v = g_s[b * CIN_ + tid];
            s2[tid] = v * v;
        }
        __syncthreads();
        const int lane = tid & 31, wp = tid >> 5;   // 16 warps x 32 co
        for (int cc = 0; cc < 32; ++cc) {
            const int co = wp * 32 + cc;
            const float4* wq = (const float4*)(g_wsq + (size_t)co * 512);
            float acc = 0.f;
#pragma unroll
            for (int m = 0; m < 4; ++m) {
                float4 v  = wq[lane + 32 * m];
                float4 s4 = ((const float4*)s2)[lane + 32 * m];
                acc += v.x * s4.x + v.y * s4.y + v.z * s4.z + v.w * s4.w;
            }
#pragma unroll
            for (int o = 16; o; o >>= 1) acc += __shfl_down_sync(~0u, acc, o);
            if (lane == 0) g_d[b * COUT_ + co] = rsqrtf(acc + 1e-8f);
        }
        return;
    }
    if (r == 34) {
        // guard zeroing: slice b of the 196608 guard halves
        const __half z = __float2half_rn(0.f);
        const int base = b * 12288;
        for (int k = tid; k < 12288; k += 512) {
            int idx = base + k;
            if (idx < XGUARD * 512)
                g_Xh[idx] = z;
            else
                g_Xh[(size_t)(XGUARD + XROWS) * 512 + (idx - XGUARD * 512)] = z;
        }
        return;
    }

    // prepx: row n = b*1156 + r*34 + c ; Xp = x*s interior, 0 on r,c in {0,33}
    const bool irow = (r >= 1 && r <= 32);
    for (int half = 0; half < 2; ++half) {
        const int cb = half * 256;
        __syncthreads();
        if (irow) {
            for (int idx = tid; idx < 256 * 32; idx += 512) {
                int ci = idx >> 5, cc = idx & 31;
                xt[ci][cc] = x[((size_t)(b * 512 + cb + ci) * 32 + (r - 1)) * 32 + cc]
                             * g_s[b * 512 + cb + ci];
            }
        }
        __syncthreads();
        for (int idx = tid; idx < 34 * 256; idx += 512) {
            int c = idx >> 8, ci = idx & 255;
            float v = (irow && c >= 1 && c <= 32) ? xt[ci][c - 1] : 0.f;
            size_t o = ((size_t)(b * 1156 + r * 34 + c) + XGUARD) * 512 + cb + ci;
            g_Xh[o] = __float2half_rn(v);
        }
    }
}

// ---------------------------------------------------------------------------
// Launch 3: GEMM (byte-identical to the 703/677us champion).
#define STAGES      4
#define TILE_A      0           // 128 x 64 fp16 = 16KB
#define TILE_B      16384       // 256 x 64 fp16 = 32KB
#define STAGE_BYTES 49152
#define NCHUNK      72          // 9 taps x 8 chunks of 64 ci

__device__ __forceinline__ void load_chunk(uint32_t su, int stage, int g,
                                           int co0, int n0, int tid) {
    const int tap = c_tap[g >> 3];
    const int kc  = (g & 7) << 6;
    const uint32_t sb = su + stage * STAGE_BYTES;
#pragma unroll
    for (int t = 0; t < 4; ++t) {
        int idx = t * 256 + tid;
        int row = idx >> 3, c8 = idx & 7;
        size_t aoff = ((size_t)(tap * 512 + co0 + row)) * 512 + kc + c8 * 8;
        cp16(sb + TILE_A + swz(row, c8), g_Ah + aoff);
    }
    const long base = (long)n0 - c_shift[tap] + XGUARD;
#pragma unroll
    for (int t = 0; t < 8; ++t) {
        int idx = t * 256 + tid;
        int row = idx >> 3, c8 = idx & 7;
        size_t boff = (size_t)(base + row) * 512 + kc + c8 * 8;
        cp16(sb + TILE_B + swz(row, c8), g_Xh + boff);
    }
}

__device__ __forceinline__ void do_compute(uint32_t sb, float acc[4][8][4],
                                           int lane, int warp_m, int warp_n) {
#pragma unroll
    for (int ks = 0; ks < 4; ++ks) {
        uint32_t bh[16];
#pragma unroll
        for (int pr = 0; pr < 4; ++pr) {
            int brow = warp_n + pr * 16 + (lane & 7) + ((lane >> 4) & 1) * 8;
            int bc8  = ks * 2 + ((lane >> 3) & 1);
            ldsm_x4(&bh[pr * 4], sb + TILE_B + swz(brow, bc8));
        }
#pragma unroll
        for (int mt = 0; mt < 4; ++mt) {
            int arow = warp_m + mt * 16 + (lane & 15);
            int ac8  = ks * 2 + ((lane >> 4) & 1);
            uint32_t ah[4];
            ldsm_x4(ah, sb + TILE_A + swz(arow, ac8));
#pragma unroll
            for (int nt = 0; nt < 8; ++nt) {
                mma_fp16(acc[mt][nt], ah, &bh[(nt >> 1) * 4 + (nt & 1) * 2]);
            }
        }
    }
}

__device__ __forceinline__ void epilogue(float acc[4][8][4], int p, int co0,
                                         int n0, int lane, int warp_m, int warp_n) {
    const int rr = lane >> 2, q = lane & 3;
#pragma unroll
    for (int mt = 0; mt < 4; ++mt) {
        const int co = co0 + warp_m + mt * 16 + rr;
#pragma unroll
        for (int nt = 0; nt < 8; ++nt) {
            int n = n0 + warp_n + nt * 8 + q * 2;
            if (n < XROWS) {
                int b = n / 1156;
                int rem = n - b * 1156;   // even: half2 stays in-row and aligned
                __half2 v0 = __floats2half2_rn(acc[mt][nt][0], acc[mt][nt][1]);
                __half2 v1 = __floats2half2_rn(acc[mt][nt][2], acc[mt][nt][3]);
                *(__half2*)(g_y + (((size_t)(b * 512 + co) * 4 + p) * 1156 + rem)) = v0;
                *(__half2*)(g_y + (((size_t)(b * 512 + co + 8) * 4 + p) * 1156 + rem)) = v1;
            }
        }
    }
}

__global__ __launch_bounds__(256, 1) void k_gemm() {
    extern __shared__ char smem[];
    const uint32_t su = smem_to_u32(smem);
    const int tid = threadIdx.x;
    const int lane = tid & 31, wid = tid >> 5;
    const int warp_m = (wid >> 2) * 64;
    const int warp_n = (wid & 3) * 64;
    const int n0  = blockIdx.x * 256;
    const int co0 = blockIdx.y * 128;

    float acc[4][8][4];
#pragma unroll
    for (int a = 0; a < 4; ++a)
#pragma unroll
        for (int b = 0; b < 8; ++b)
#pragma unroll
            for (int c = 0; c < 4; ++c) acc[a][b][c] = 0.f;

#pragma unroll
    for (int s = 0; s < STAGES - 1; ++s) {
        load_chunk(su, s, s, co0, n0, tid);
        cp_commit();
    }

    for (int g = 0; g < NCHUNK; ++g) {
        cp_wait2();
        __syncthreads();
        if (g + STAGES - 1 < NCHUNK)
            load_chunk(su, (g + STAGES - 1) % STAGES, g + STAGES - 1, co0, n0, tid);
        cp_commit();
        do_compute(su + (g % STAGES) * STAGE_BYTES, acc, lane, warp_m, warp_n);
        if (g == 31 || g == 47 || g == 63 || g == 71) {
            const int p = (g == 31) ? 0 : (g == 47) ? 1 : (g == 63) ? 2 : 3;
            epilogue(acc, p, co0, n0, lane, warp_m, warp_n);
#pragma unroll
            for (int a = 0; a < 4; ++a)
#pragma unroll
                for (int b = 0; b < 8; ++b)
#pragma unroll
                    for (int c = 0; c < 4; ++c) acc[a][b][c] = 0.f;
        }
    }
}

// ---------------------------------------------------------------------------
// Launch 4 (profiled): blur v2.
// Demux: half2 loads over full 34-wide rows. g_y row 0 / col 0 are exactly
// zero (they sample only the zero border of Xp), so writes are unconditional
// except the single col=-1 case; col-0 border zeroing is implicit.
// Vertical: float4 row loads (20 LDS.128 vs 76 LDS.32). Output: 4 STG.128.
__global__ __launch_bounds__(256, 4) void k_blur(float* __restrict__ z,
                                                 const float* __restrict__ bias) {
    __shared__ float ys[67][68];
    const int co = blockIdx.x, b = blockIdx.y;
    const int tid = threadIdx.x;

    if (tid < 68) ys[0][tid] = 0.f;        // row 0 only; col 0 via demux zeros
    __syncthreads();

    const __half2* yb2 = (const __half2*)(g_y + ((size_t)(b * 512 + co)) * 4 * 1156);
#pragma unroll
    for (int p = 0; p < 4; ++p) {
        const int a = p >> 1, c = p & 1;
        const __half2* yp = yb2 + p * 578;           // p*1156 halves
        for (int item = tid; item < 561; item += 256) {   // 33 rows x 17 half2
            int i = item / 17;                        // const-div (mul/shift)
            int k = item - i * 17;
            float2 f = __half22float2(yp[(i + 1) * 17 + k]);
            int row  = 2 * i + a + 1;
            int col0 = 4 * k + c - 1;                 // jj=2k -> col 2*jj+c-1
            if (col0 >= 0) ys[row][col0] = f.x;       // only k=0,c=0 skipped
            ys[row][col0 + 2] = f.y;                  // jj=2k+1
        }
    }
    __syncthreads();

    const float scale = g_d[b * COUT_ + co] * (1.f / 16.f);
    const float bv = bias[co];
    const int u  = tid >> 2;          // 0..63
    const int v0 = (tid & 3) * 16;    // 16 outputs per thread

    float colv[19];
#pragma unroll
    for (int d = 0; d < 4; ++d) {
        const float4* rp = (const float4*)&ys[u + d][v0];
#pragma unroll
        for (int q = 0; q < 5; ++q) {
            float4 v = rp[q];
            float e[4] = {v.x, v.y, v.z, v.w};
#pragma unroll
            for (int ee = 0; ee < 4; ++ee) {
                int m = 4 * q + ee;
                if (m < 19) {
                    if (d == 0)      colv[m] = e[ee];
                    else if (d == 3) colv[m] += e[ee];
                    else             colv[m] = fmaf(3.f, e[ee], colv[m]);
                }
            }
        }
    }

    float out[16];
#pragma unroll
    for (int m = 0; m < 16; ++m) {
        float h = (colv[m] + colv[m + 3]) + 3.f * (colv[m + 1] + colv[m + 2]);
        out[m] = fmaf(h, scale, bv);
    }
    float4* zp = (float4*)(z + (((size_t)b * COUT_ + co) * 64 + u) * 64 + v0);
#pragma unroll
    for (int q = 0; q < 4; ++q)
        zp[q] = make_float4(out[4 * q], out[4 * q + 1], out[4 * q + 2], out[4 * q + 3]);
}

// ---------------------------------------------------------------------------
extern "C" void kernel_launch(void* const* d_in, const int* in_sizes, int n_in,
                              void* d_out, int out_size) {
    const float* x    = (const float*)d_in[0];
    const float* w    = (const float*)d_in[1];
    const float* wt   = (const float*)d_in[2];
    const float* bias = (const float*)d_in[3];
    const float* aw   = (const float*)d_in[4];
    const float* ab   = (const float*)d_in[5];
    float* z = (float*)d_out;

    cudaFuncSetAttribute(k_gemm, cudaFuncAttributeMaxDynamicSharedMemorySize,
                         STAGES * STAGE_BYTES);

    // 4 launches; k_blur 4th -> ncu profiles it (verify blur v2 next round).
    k_sw<<<16 + COUT_, 512>>>(w, aw, ab, wt);               // 1
    k_px<<<dim3(36, B_), 512>>>(x);                         // 2
    k_gemm<<<dim3(NT2, 4), 256, STAGES * STAGE_BYTES>>>();  // 3
    k_blur<<<dim3(COUT_, B_), 256>>>(z, bias);              // 4  <- profiled
}

// round 16
// speedup vs baseline: 1.7853x; 1.0452x over previous
#include <cuda_runtime.h>
#include <cuda_fp16.h>
#include <cstdint>

#define B_    16
#define CIN_  512
#define COUT_ 512
#define LAT_  512

#define XROWS  18496            // 16 * 34 * 34
#define XGUARD 64               // front zero rows
#define XTAIL  320              // tail zero rows (covers 256-row B tiles past end)
#define NT2    73               // ceil(18496/256)

// ---------------- device globals (allocation-free scratch) ------------------
__device__ float g_s[B_ * CIN_];
__device__ float g_wsq[COUT_ * CIN_];
__device__ float g_d[B_ * COUT_];
__device__ __half g_y[(size_t)B_ * COUT_ * 4 * 1156];    // [b][co][p][34][34] fp16

__device__ __align__(256) __half g_Ah[9ull * 512 * 512];   // [tap][co][ci]
__device__ __align__(256) __half g_Xh[(size_t)(XGUARD + XROWS + XTAIL) * 512];

// tap order grouped by parity: p0={0,2,6,8} p1={1,7} p2={3,5} p3={4}
__constant__ int c_tap[9]   = {0, 2, 6, 8, 1, 7, 3, 5, 4};
// shift[t] = (kh>>1)*34 + (kw>>1), indexed by tap id
__constant__ int c_shift[9] = {0, 0, 1, 0, 0, 1, 34, 34, 35};

// ---------------- helpers ---------------------------------------------------
__device__ __forceinline__ uint32_t smem_to_u32(const void* p) {
    uint32_t a;
    asm("{ .reg .u64 t; cvta.to.shared.u64 t, %1; cvt.u32.u64 %0, t; }"
        : "=r"(a) : "l"(p));
    return a;
}
__device__ __forceinline__ void cp16(uint32_t dst, const void* src) {
    asm volatile("cp.async.cg.shared.global [%0], [%1], 16;\n"
                 :: "r"(dst), "l"(src));
}
__device__ __forceinline__ void cp_commit() {
    asm volatile("cp.async.commit_group;\n" ::: "memory");
}
__device__ __forceinline__ void cp_wait2() {
    asm volatile("cp.async.wait_group 2;\n" ::: "memory");
}
__device__ __forceinline__ void ldsm_x4(uint32_t* r, uint32_t addr) {
    asm volatile("ldmatrix.sync.aligned.m8n8.x4.shared.b16 {%0,%1,%2,%3}, [%4];"
                 : "=r"(r[0]), "=r"(r[1]), "=r"(r[2]), "=r"(r[3]) : "r"(addr));
}
__device__ __forceinline__ void mma_fp16(float* d, const uint32_t* a,
                                         const uint32_t* b) {
    asm volatile(
        "mma.sync.aligned.m16n8k16.row.col.f32.f16.f16.f32 "
        "{%0,%1,%2,%3}, {%4,%5,%6,%7}, {%8,%9}, {%0,%1,%2,%3};"
        : "+f"(d[0]), "+f"(d[1]), "+f"(d[2]), "+f"(d[3])
        : "r"(a[0]), "r"(a[1]), "r"(a[2]), "r"(a[3]), "r"(b[0]), "r"(b[1]));
}
// smem tile rows of 64 fp16 (128B), xor-swizzled 16B chunks, 8-row period
__device__ __forceinline__ int swz(int row, int c8) {
    return row * 128 + ((c8 ^ (row & 7)) << 4);
}

// ---------------------------------------------------------------------------
// Launch 1: style (blocks 0..15, warp-cooperative coalesced) +
//           prepw/wsq (blocks 16..527)
__global__ __launch_bounds__(512) void k_sw(const float* __restrict__ w,
                                            const float* __restrict__ aw,
                                            const float* __restrict__ ab,
                                            const float* __restrict__ weight) {
    const int bx = blockIdx.x, tid = threadIdx.x;
    if (bx < 16) {
        __shared__ float sw[512];
        const int b = bx;
        sw[tid] = w[b * 512 + tid];
        __syncthreads();
        const int lane = tid & 31, wp = tid >> 5;   // 16 warps x 32 ci
        for (int cc = 0; cc < 32; ++cc) {
            const int ci = wp * 32 + cc;
            const float4* ar = (const float4*)(aw + (size_t)ci * 512);
            float acc = 0.f;
#pragma unroll
            for (int m = 0; m < 4; ++m) {
                float4 v  = ar[lane + 32 * m];
                float4 s4 = ((const float4*)sw)[lane + 32 * m];
                acc += v.x * s4.x + v.y * s4.y + v.z * s4.z + v.w * s4.w;
            }
#pragma unroll
            for (int o = 16; o; o >>= 1) acc += __shfl_down_sync(~0u, acc, o);
            if (lane == 0) g_s[b * 512 + ci] = acc + ab[ci] + 1.0f;
        }
    } else {
        // prepw: g_Ah[tap][co][ci] = fp16(weight[co][ci][tap]); wsq = sum w^2
        const int co = bx - 16, ci = tid;
        const float* p = weight + ((size_t)co * 512 + ci) * 9;
        float sq = 0.f;
#pragma unroll
        for (int t = 0; t < 9; ++t) {
            float v = p[t];
            g_Ah[((size_t)t * 512 + co) * 512 + ci] = __float2half_rn(v);
            sq += v * v;
        }
        g_wsq[(size_t)co * 512 + ci] = sq;
    }
}

// ---------------------------------------------------------------------------
// Launch 2: prepx (x=0..33) + guard (x==34) + demod (x==35, warp-coop);
// grid (36, B_)
__global__ __launch_bounds__(512) void k_px(const float* __restrict__ x) {
    __shared__ float xt[256][33];
    const int r = blockIdx.x;
    const int b = blockIdx.y;
    const int tid = threadIdx.x;

    if (r == 35) {
        // demod: d[b,co] = rsqrt(sum_ci s^2 * wsq + 1e-8), coalesced
        __shared__ float s2[CIN_];
        {
            float v = g_s[b * CIN_ + tid];
            s2[tid] = v * v;
        }
        __syncthreads();
        const int lane = tid & 31, wp = tid >> 5;   // 16 warps x 32 co
        for (int cc = 0; cc < 32; ++cc) {
            const int co = wp * 32 + cc;
            const float4* wq = (const float4*)(g_wsq + (size_t)co * 512);
            float acc = 0.f;
#pragma unroll
            for (int m = 0; m < 4; ++m) {
                float4 v  = wq[lane + 32 * m];
                float4 s4 = ((const float4*)s2)[lane + 32 * m];
                acc += v.x * s4.x + v.y * s4.y + v.z * s4.z + v.w * s4.w;
            }
#pragma unroll
            for (int o = 16; o; o >>= 1) acc += __shfl_down_sync(~0u, acc, o);
            if (lane == 0) g_d[b * COUT_ + co] = rsqrtf(acc + 1e-8f);
        }
        return;
    }
    if (r == 34) {
        // guard zeroing: slice b of the 196608 guard halves
        const __half z = __float2half_rn(0.f);
        const int base = b * 12288;
        for (int k = tid; k < 12288; k += 512) {
            int idx = base + k;
            if (idx < XGUARD * 512)
                g_Xh[idx] = z;
            else
                g_Xh[(size_t)(XGUARD + XROWS) * 512 + (idx - XGUARD * 512)] = z;
        }
        return;
    }

    // prepx: row n = b*1156 + r*34 + c ; Xp = x*s interior, 0 on r,c in {0,33}
    const bool irow = (r >= 1 && r <= 32);
    for (int half = 0; half < 2; ++half) {
        const int cb = half * 256;
        __syncthreads();
        if (irow) {
            for (int idx = tid; idx < 256 * 32; idx += 512) {
                int ci = idx >> 5, cc = idx & 31;
                xt[ci][cc] = x[((size_t)(b * 512 + cb + ci) * 32 + (r - 1)) * 32 + cc]
                             * g_s[b * 512 + cb + ci];
            }
        }
        __syncthreads();
        for (int idx = tid; idx < 34 * 256; idx += 512) {
            int c = idx >> 8, ci = idx & 255;
            float v = (irow && c >= 1 && c <= 32) ? xt[ci][c - 1] : 0.f;
            size_t o = ((size_t)(b * 1156 + r * 34 + c) + XGUARD) * 512 + cb + ci;
            g_Xh[o] = __float2half_rn(v);
        }
    }
}

// ---------------------------------------------------------------------------
// Launch 3: GEMM (byte-identical to the champion).
#define STAGES      4
#define TILE_A      0           // 128 x 64 fp16 = 16KB
#define TILE_B      16384       // 256 x 64 fp16 = 32KB
#define STAGE_BYTES 49152
#define NCHUNK      72          // 9 taps x 8 chunks of 64 ci

__device__ __forceinline__ void load_chunk(uint32_t su, int stage, int g,
                                           int co0, int n0, int tid) {
    const int tap = c_tap[g >> 3];
    const int kc  = (g & 7) << 6;
    const uint32_t sb = su + stage * STAGE_BYTES;
#pragma unroll
    for (int t = 0; t < 4; ++t) {
        int idx = t * 256 + tid;
        int row = idx >> 3, c8 = idx & 7;
        size_t aoff = ((size_t)(tap * 512 + co0 + row)) * 512 + kc + c8 * 8;
        cp16(sb + TILE_A + swz(row, c8), g_Ah + aoff);
    }
    const long base = (long)n0 - c_shift[tap] + XGUARD;
#pragma unroll
    for (int t = 0; t < 8; ++t) {
        int idx = t * 256 + tid;
        int row = idx >> 3, c8 = idx & 7;
        size_t boff = (size_t)(base + row) * 512 + kc + c8 * 8;
        cp16(sb + TILE_B + swz(row, c8), g_Xh + boff);
    }
}

__device__ __forceinline__ void do_compute(uint32_t sb, float acc[4][8][4],
                                           int lane, int warp_m, int warp_n) {
#pragma unroll
    for (int ks = 0; ks < 4; ++ks) {
        uint32_t bh[16];
#pragma unroll
        for (int pr = 0; pr < 4; ++pr) {
            int brow = warp_n + pr * 16 + (lane & 7) + ((lane >> 4) & 1) * 8;
            int bc8  = ks * 2 + ((lane >> 3) & 1);
            ldsm_x4(&bh[pr * 4], sb + TILE_B + swz(brow, bc8));
        }
#pragma unroll
        for (int mt = 0; mt < 4; ++mt) {
            int arow = warp_m + mt * 16 + (lane & 15);
            int ac8  = ks * 2 + ((lane >> 4) & 1);
            uint32_t ah[4];
            ldsm_x4(ah, sb + TILE_A + swz(arow, ac8));
#pragma unroll
            for (int nt = 0; nt < 8; ++nt) {
                mma_fp16(acc[mt][nt], ah, &bh[(nt >> 1) * 4 + (nt & 1) * 2]);
            }
        }
    }
}

__device__ __forceinline__ void epilogue(float acc[4][8][4], int p, int co0,
                                         int n0, int lane, int warp_m, int warp_n) {
    const int rr = lane >> 2, q = lane & 3;
#pragma unroll
    for (int mt = 0; mt < 4; ++mt) {
        const int co = co0 + warp_m + mt * 16 + rr;
#pragma unroll
        for (int nt = 0; nt < 8; ++nt) {
            int n = n0 + warp_n + nt * 8 + q * 2;
            if (n < XROWS) {
                int b = n / 1156;
                int rem = n - b * 1156;   // even: half2 stays in-row and aligned
                __half2 v0 = __floats2half2_rn(acc[mt][nt][0], acc[mt][nt][1]);
                __half2 v1 = __floats2half2_rn(acc[mt][nt][2], acc[mt][nt][3]);
                *(__half2*)(g_y + (((size_t)(b * 512 + co) * 4 + p) * 1156 + rem)) = v0;
                *(__half2*)(g_y + (((size_t)(b * 512 + co + 8) * 4 + p) * 1156 + rem)) = v1;
            }
        }
    }
}

__global__ __launch_bounds__(256, 1) void k_gemm() {
    extern __shared__ char smem[];
    const uint32_t su = smem_to_u32(smem);
    const int tid = threadIdx.x;
    const int lane = tid & 31, wid = tid >> 5;
    const int warp_m = (wid >> 2) * 64;
    const int warp_n = (wid & 3) * 64;
    const int n0  = blockIdx.x * 256;
    const int co0 = blockIdx.y * 128;

    float acc[4][8][4];
#pragma unroll
    for (int a = 0; a < 4; ++a)
#pragma unroll
        for (int b = 0; b < 8; ++b)
#pragma unroll
            for (int c = 0; c < 4; ++c) acc[a][b][c] = 0.f;

#pragma unroll
    for (int s = 0; s < STAGES - 1; ++s) {
        load_chunk(su, s, s, co0, n0, tid);
        cp_commit();
    }

    for (int g = 0; g < NCHUNK; ++g) {
        cp_wait2();
        __syncthreads();
        if (g + STAGES - 1 < NCHUNK)
            load_chunk(su, (g + STAGES - 1) % STAGES, g + STAGES - 1, co0, n0, tid);
        cp_commit();
        do_compute(su + (g % STAGES) * STAGE_BYTES, acc, lane, warp_m, warp_n);
        if (g == 31 || g == 47 || g == 63 || g == 71) {
            const int p = (g == 31) ? 0 : (g == 47) ? 1 : (g == 63) ? 2 : 3;
            epilogue(acc, p, co0, n0, lane, warp_m, warp_n);
#pragma unroll
            for (int a = 0; a < 4; ++a)
#pragma unroll
                for (int b = 0; b < 8; ++b)
#pragma unroll
                    for (int c = 0; c < 4; ++c) acc[a][b][c] = 0.f;
        }
    }
}

// ---------------------------------------------------------------------------
// Launch 4 (profiled): blur v3 — register-streamed epilogue.
// Demux unchanged from v2. Vertical+horizontal fused with a rolling 2-chunk
// window; outputs stored per-group (no colv[19]+out[16] held live) so regs
// fit 6 CTAs/SM for latency hiding.
__global__ __launch_bounds__(256, 6) void k_blur(float* __restrict__ z,
                                                 const float* __restrict__ bias) {
    __shared__ float ys[67][68];
    const int co = blockIdx.x, b = blockIdx.y;
    const int tid = threadIdx.x;

    if (tid < 68) ys[0][tid] = 0.f;   // demux writes only rows >=1: no sync needed

    const __half2* yb2 = (const __half2*)(g_y + ((size_t)(b * 512 + co)) * 4 * 1156);
#pragma unroll
    for (int p = 0; p < 4; ++p) {
        const int a = p >> 1, c = p & 1;
        const __half2* yp = yb2 + p * 578;           // p*1156 halves
        for (int item = tid; item < 561; item += 256) {   // 33 rows x 17 half2
            int i = item / 17;                        // const-div (mul/shift)
            int k = item - i * 17;
            float2 f = __half22float2(yp[(i + 1) * 17 + k]);
            int row  = 2 * i + a + 1;
            int col0 = 4 * k + c - 1;
            if (col0 >= 0) ys[row][col0] = f.x;       // only k=0,c=0 skipped
            ys[row][col0 + 2] = f.y;
        }
    }
    __syncthreads();

    const float scale = g_d[b * COUT_ + co] * (1.f / 16.f);
    const float bv = bias[co];
    const int u  = tid >> 2;          // 0..63
    const int v0 = (tid & 3) * 16;    // 16 outputs per thread

    float4* zp = (float4*)(z + (((size_t)b * COUT_ + co) * 64 + u) * 64 + v0);

    float cprev[4];
#pragma unroll
    for (int q = 0; q < 5; ++q) {
        // vertical pass on column chunk q (cols v0+4q .. v0+4q+3)
        float4 r0 = *(const float4*)&ys[u][v0 + 4 * q];
        float4 r1 = *(const float4*)&ys[u + 1][v0 + 4 * q];
        float4 r2 = *(const float4*)&ys[u + 2][v0 + 4 * q];
        float4 r3 = *(const float4*)&ys[u + 3][v0 + 4 * q];
        float ccur[4];
        ccur[0] = (r0.x + r3.x) + 3.f * (r1.x + r2.x);
        ccur[1] = (r0.y + r3.y) + 3.f * (r1.y + r2.y);
        ccur[2] = (r0.z + r3.z) + 3.f * (r1.z + r2.z);
        ccur[3] = (r0.w + r3.w) + 3.f * (r1.w + r2.w);
        if (q > 0) {
            // horizontal pass: outputs group q-1 from window cprev||ccur
            float wv[8] = {cprev[0], cprev[1], cprev[2], cprev[3],
                           ccur[0],  ccur[1],  ccur[2],  ccur[3]};
            float4 o;
            o.x = fmaf((wv[0] + wv[3]) + 3.f * (wv[1] + wv[2]), scale, bv);
            o.y = fmaf((wv[1] + wv[4]) + 3.f * (wv[2] + wv[3]), scale, bv);
            o.z = fmaf((wv[2] + wv[5]) + 3.f * (wv[3] + wv[4]), scale, bv);
            o.w = fmaf((wv[3] + wv[6]) + 3.f * (wv[4] + wv[5]), scale, bv);
            zp[q - 1] = o;
        }
#pragma unroll
        for (int e = 0; e < 4; ++e) cprev[e] = ccur[e];
    }
}

// ---------------------------------------------------------------------------
extern "C" void kernel_launch(void* const* d_in, const int* in_sizes, int n_in,
                              void* d_out, int out_size) {
    const float* x    = (const float*)d_in[0];
    const float* w    = (const float*)d_in[1];
    const float* wt   = (const float*)d_in[2];
    const float* bias = (const float*)d_in[3];
    const float* aw   = (const float*)d_in[4];
    const float* ab   = (const float*)d_in[5];
    float* z = (float*)d_out;

    cudaFuncSetAttribute(k_gemm, cudaFuncAttributeMaxDynamicSharedMemorySize,
                         STAGES * STAGE_BYTES);

    // 4 launches; k_blur 4th -> ncu profiles it (verify blur v3).
    k_sw<<<16 + COUT_, 512>>>(w, aw, ab, wt);               // 1
    k_px<<<dim3(36, B_), 512>>>(x);                         // 2
    k_gemm<<<dim3(NT2, 4), 256, STAGES * STAGE_BYTES>>>();  // 3
    k_blur<<<dim3(COUT_, B_), 256>>>(z, bias);              // 4  <- profiled
}